// round 5
// baseline (speedup 1.0000x reference)
#include <cuda_runtime.h>
#include <math.h>
#include <stdint.h>

// ---------------------------------------------------------------------------
// LSTMEncDec — R5: K-permuted, pre-split (tf32 hi + fp32-residual lo) operand
// planes enable LDS.128 fragment loads with zero in-loop split ALU. Split-K=4
// for the big video GEMM kills wave-quantization. Persistent recurrence kept.
// Numerics identical to R4 (same 3-term tf32 products).
// ---------------------------------------------------------------------------

namespace cfg {
constexpr int B = 64, NC = 5, L = 20, F = 20, C = 8192, E = 300;
constexpr int H = 512, G4 = 2048;
constexpr int MT = B * NC;           // 320
constexpr int EP = 320;              // E padded
constexpr int BH = B * H;            // 32768
constexpr int MH = MT * H;           // 163840
constexpr int NBLK = 320;

constexpr size_t OFF_GVP  = 0;                                   // 4 partials
constexpr size_t OFF_GV   = OFF_GVP  + 4ull * 1280 * 2048;
constexpr size_t OFF_GT   = OFF_GV   + (size_t)1280 * 2048;
constexpr size_t OFF_XTH  = OFF_GT   + (size_t)6400 * 2048;
constexpr size_t OFF_XTL  = OFF_XTH  + (size_t)6400 * EP;
constexpr size_t OFF_WT1H = OFF_XTL  + (size_t)6400 * EP;
constexpr size_t OFF_WT1L = OFF_WT1H + (size_t)G4 * EP;
constexpr size_t OFF_VFH  = OFF_WT1L + (size_t)G4 * EP;
constexpr size_t OFF_VFL  = OFF_VFH  + (size_t)1280 * C;
constexpr size_t OFF_WV1H = OFF_VFL  + (size_t)1280 * C;
constexpr size_t OFF_WV1L = OFF_WV1H + (size_t)G4 * C;
constexpr size_t OFF_W512 = OFF_WV1L + (size_t)G4 * C;  // 12 planes of G4*512:
// order: WHHV1 h,l | WIHV2 h,l | WHHV2 h,l | WHHT1 h,l | WIHT2 h,l | WHHT2 h,l
constexpr size_t SZW      = (size_t)G4 * 512;
constexpr size_t OFF_D1H  = OFF_W512 + 12 * SZW;
constexpr size_t OFF_D1L  = OFF_D1H  + (size_t)1024 * 1024;
constexpr size_t OFF_VSA  = OFF_D1L  + (size_t)1024 * 1024;  // 6 planes x BH
constexpr size_t OFF_VSB  = OFF_VSA  + 6ull * BH;
constexpr size_t OFF_VRH  = OFF_VSB  + 6ull * BH;
constexpr size_t OFF_VRL  = OFF_VRH  + (size_t)BH;
constexpr size_t OFF_TSA  = OFF_VRL  + (size_t)BH;           // 6 planes x MH
constexpr size_t OFF_TSB  = OFF_TSA  + 6ull * MH;
constexpr size_t OFF_TRH  = OFF_TSB  + 6ull * MH;
constexpr size_t OFF_TRL  = OFF_TRH  + (size_t)MH;
constexpr size_t OFF_STH  = OFF_TRL  + (size_t)MH;
constexpr size_t OFF_STL  = OFF_STH  + (size_t)MT * 1024;
constexpr size_t OFF_FE   = OFF_STL  + (size_t)MT * 1024;
constexpr size_t OFF_OUT  = OFF_FE   + (size_t)MT * 1024;
constexpr size_t TOTAL    = OFF_OUT  + (size_t)MT;
}  // namespace cfg

__device__ __align__(256) float g_scratch[cfg::TOTAL];
__device__ unsigned g_bars[128];

__device__ __forceinline__ float sigm(float x) { return 1.f / (1.f + expf(-x)); }

// perm16 is an involution: swaps the two 2-bit fields of k%16.
__host__ __device__ __forceinline__ int perm16(int k) {
    return (k & ~15) | ((k & 3) << 2) | ((k >> 2) & 3);
}

__device__ __forceinline__ void fsplit(float x, float& hi, float& lo) {
    uint32_t h = __float_as_uint(x) & 0xFFFFE000u;
    hi = __uint_as_float(h);
    lo = x - hi;
}

__device__ __forceinline__ void cp_async16(void* smem, const void* gmem) {
    uint32_t s = (uint32_t)__cvta_generic_to_shared(smem);
    asm volatile("cp.async.cg.shared.global [%0], [%1], 16;\n" :: "r"(s), "l"(gmem));
}
#define CP_COMMIT asm volatile("cp.async.commit_group;\n" ::: "memory")
#define CP_WAIT0  asm volatile("cp.async.wait_group 0;\n" ::: "memory")
#define CP_WAIT1  asm volatile("cp.async.wait_group 1;\n" ::: "memory")

__device__ __forceinline__ void mma8(float* c, const uint32_t* a, uint32_t b0, uint32_t b1) {
    asm volatile(
        "mma.sync.aligned.m16n8k8.row.col.f32.tf32.tf32.f32 "
        "{%0,%1,%2,%3}, {%4,%5,%6,%7}, {%8,%9}, {%0,%1,%2,%3};"
        : "+f"(c[0]), "+f"(c[1]), "+f"(c[2]), "+f"(c[3])
        : "r"(a[0]), "r"(a[1]), "r"(a[2]), "r"(a[3]), "r"(b0), "r"(b1));
}

__device__ __forceinline__ void gridbar(int idx) {
    __syncthreads();
    if (threadIdx.x == 0) {
        __threadfence();
        atomicAdd(&g_bars[idx], 1u);
        while (*((volatile unsigned*)&g_bars[idx]) < (unsigned)cfg::NBLK) {}
        __threadfence();
    }
    __syncthreads();
}

// ---------------------------------------------------------------------------
// Tensor GEMM on pre-split, K-permuted planes.
// C[M,N] = A@W^T (+bias). 256 thr, tile 64x128, BK=16, dist-2 cp.async.
// blockIdx.z = K-slice (len KL, out partial at Cmat + z*M*N).
// ---------------------------------------------------------------------------
__global__ void __launch_bounds__(256) gemm3_tc(
    const float* __restrict__ Ah, const float* __restrict__ Al,
    const float* __restrict__ Wh, const float* __restrict__ Wl,
    const float* __restrict__ bias, float* __restrict__ Cmat,
    int M, int N, int Ks, int KL)
{
    __shared__ __align__(16) float sAh[2][64][16];
    __shared__ __align__(16) float sAl[2][64][16];
    __shared__ __align__(16) float sBh[2][128][16];
    __shared__ __align__(16) float sBl[2][128][16];
    const int tid = threadIdx.x;
    const int lane = tid & 31, warp = tid >> 5;
    const int wm = warp & 1, wn = warp >> 1;
    const int g8 = lane >> 2, t4 = lane & 3;
    const int bm = blockIdx.y * 64, bn = blockIdx.x * 128;
    const int koff = blockIdx.z * KL;
    float* Cout = Cmat + (size_t)blockIdx.z * M * N;

    float acc[2][4][4] = {};
    const int NCH = KL / 16;

    auto issue = [&](int c, int buf) {
        const int kpos = koff + c * 16;
        {
            int r = tid >> 2, k4 = (tid & 3) << 2;
            cp_async16(&sAh[buf][r][k4], Ah + (size_t)(bm + r) * Ks + kpos + k4);
            cp_async16(&sAl[buf][r][k4], Al + (size_t)(bm + r) * Ks + kpos + k4);
        }
#pragma unroll
        for (int q = 0; q < 2; q++) {
            int v = tid + q * 256;
            int r = v >> 2, k4 = (v & 3) << 2;
            cp_async16(&sBh[buf][r][k4], Wh + (size_t)(bn + r) * Ks + kpos + k4);
            cp_async16(&sBl[buf][r][k4], Wl + (size_t)(bn + r) * Ks + kpos + k4);
        }
    };

    issue(0, 0); CP_COMMIT;
    issue(1, 1); CP_COMMIT;
    for (int c = 0; c < NCH; c++) {
        if (c < NCH - 1) { CP_WAIT1; } else { CP_WAIT0; }
        __syncthreads();
        const int buf = c & 1;
        uint4 fAh[2][2], fAl[2][2];
#pragma unroll
        for (int mt = 0; mt < 2; mt++) {
            int r = wm * 32 + mt * 16 + g8;
            fAh[mt][0] = *reinterpret_cast<const uint4*>(&sAh[buf][r][t4 * 4]);
            fAh[mt][1] = *reinterpret_cast<const uint4*>(&sAh[buf][r + 8][t4 * 4]);
            fAl[mt][0] = *reinterpret_cast<const uint4*>(&sAl[buf][r][t4 * 4]);
            fAl[mt][1] = *reinterpret_cast<const uint4*>(&sAl[buf][r + 8][t4 * 4]);
        }
#pragma unroll
        for (int nh = 0; nh < 2; nh++) {
            uint4 fBh[2], fBl[2];
#pragma unroll
            for (int i = 0; i < 2; i++) {
                int n = wn * 32 + (nh * 2 + i) * 8 + g8;
                fBh[i] = *reinterpret_cast<const uint4*>(&sBh[buf][n][t4 * 4]);
                fBl[i] = *reinterpret_cast<const uint4*>(&sBl[buf][n][t4 * 4]);
            }
#pragma unroll
            for (int kk = 0; kk < 2; kk++) {
                uint32_t ah[2][4], al[2][4];
#pragma unroll
                for (int mt = 0; mt < 2; mt++) {
                    if (kk == 0) {
                        ah[mt][0] = fAh[mt][0].x; ah[mt][1] = fAh[mt][1].x;
                        ah[mt][2] = fAh[mt][0].y; ah[mt][3] = fAh[mt][1].y;
                        al[mt][0] = fAl[mt][0].x; al[mt][1] = fAl[mt][1].x;
                        al[mt][2] = fAl[mt][0].y; al[mt][3] = fAl[mt][1].y;
                    } else {
                        ah[mt][0] = fAh[mt][0].z; ah[mt][1] = fAh[mt][1].z;
                        ah[mt][2] = fAh[mt][0].w; ah[mt][3] = fAh[mt][1].w;
                        al[mt][0] = fAl[mt][0].z; al[mt][1] = fAl[mt][1].z;
                        al[mt][2] = fAl[mt][0].w; al[mt][3] = fAl[mt][1].w;
                    }
                }
#pragma unroll
                for (int i = 0; i < 2; i++) {
                    uint32_t bh0 = kk ? fBh[i].z : fBh[i].x;
                    uint32_t bh1 = kk ? fBh[i].w : fBh[i].y;
                    uint32_t bl0 = kk ? fBl[i].z : fBl[i].x;
                    uint32_t bl1 = kk ? fBl[i].w : fBl[i].y;
                    const int nt = nh * 2 + i;
#pragma unroll
                    for (int mt = 0; mt < 2; mt++) {
                        mma8(acc[mt][nt], ah[mt], bh0, bh1);
                        mma8(acc[mt][nt], ah[mt], bl0, bl1);
                        mma8(acc[mt][nt], al[mt], bh0, bh1);
                    }
                }
            }
        }
        __syncthreads();
        if (c + 2 < NCH) { issue(c + 2, buf); CP_COMMIT; }
    }

#pragma unroll
    for (int mt = 0; mt < 2; mt++) {
#pragma unroll
        for (int rr = 0; rr < 2; rr++) {
            int m = bm + wm * 32 + mt * 16 + g8 + rr * 8;
#pragma unroll
            for (int nt = 0; nt < 4; nt++) {
                int n = bn + wn * 32 + nt * 8 + t4 * 2;
                float v0 = acc[mt][nt][rr * 2 + 0];
                float v1 = acc[mt][nt][rr * 2 + 1];
                if (bias) { v0 += bias[n]; v1 += bias[n + 1]; }
                *(float2*)(Cout + (size_t)m * N + n) = make_float2(v0, v1);
            }
        }
    }
}

// ---------------------------------------------------------------------------
// Persistent recurrence: step tile 32 rows x 16 j x 4 gates, pre-split planes.
// ---------------------------------------------------------------------------
struct __align__(16) StepSmem {
    float Hh[2][32][16], Hl[2][32][16];
    float Wh[2][64][16], Wl[2][64][16];
};

template <bool L2K>
__device__ __forceinline__ void step_tile(
    const float* s0h, const float* s0l, const float* W0h, const float* W0l,
    const float* s1h, const float* s1l, const float* W1h, const float* W1l,
    const float* gpre_or_bias, int t, int Tsteps,
    const float* hp_h, const float* hp_l, const float* cp,
    float* hn_h, float* hn_l, float* cn,
    float* hr_h, float* hr_l,
    const int* qlen, int m0, int j0, StepSmem* sm)
{
    const int tid = threadIdx.x;
    const int lane = tid & 31, warp = tid >> 5;
    const int wm = warp & 1, wj = warp >> 1;
    const int g8 = lane >> 2, t4 = lane & 3;
    constexpr int NCH = L2K ? 64 : 32;

    float acc[4][4] = {};

    auto issue = [&](int c, int buf) {
        const float* sh = s0h; const float* sl = s0l;
        const float* wh = W0h; const float* wl = W0l;
        int kpos = c * 16;
        if (L2K && c >= 32) { sh = s1h; sl = s1l; wh = W1h; wl = W1l; kpos -= 512; }
        {
            int r = tid >> 2, k4 = (tid & 3) << 2;
            cp_async16(&sm->Hh[buf][r][k4], sh + (size_t)(m0 + r) * 512 + kpos + k4);
            cp_async16(&sm->Hl[buf][r][k4], sl + (size_t)(m0 + r) * 512 + kpos + k4);
        }
#pragma unroll
        for (int q = 0; q < 2; q++) {
            int v = tid + q * 128;
            int r = v >> 2, k4 = (v & 3) << 2;
            int gc = (r >> 4) * 512 + j0 + (r & 15);
            cp_async16(&sm->Wh[buf][r][k4], wh + (size_t)gc * 512 + kpos + k4);
            cp_async16(&sm->Wl[buf][r][k4], wl + (size_t)gc * 512 + kpos + k4);
        }
    };

    issue(0, 0); CP_COMMIT;
    issue(1, 1); CP_COMMIT;
    for (int c = 0; c < NCH; c++) {
        if (c < NCH - 1) { CP_WAIT1; } else { CP_WAIT0; }
        __syncthreads();
        const int buf = c & 1;
        const int r = wm * 16 + g8;
        uint4 fHh0 = *reinterpret_cast<const uint4*>(&sm->Hh[buf][r][t4 * 4]);
        uint4 fHh1 = *reinterpret_cast<const uint4*>(&sm->Hh[buf][r + 8][t4 * 4]);
        uint4 fHl0 = *reinterpret_cast<const uint4*>(&sm->Hl[buf][r][t4 * 4]);
        uint4 fHl1 = *reinterpret_cast<const uint4*>(&sm->Hl[buf][r + 8][t4 * 4]);
        uint4 fBh[4], fBl[4];
#pragma unroll
        for (int gg = 0; gg < 4; gg++) {
            int n = gg * 16 + wj * 8 + g8;
            fBh[gg] = *reinterpret_cast<const uint4*>(&sm->Wh[buf][n][t4 * 4]);
            fBl[gg] = *reinterpret_cast<const uint4*>(&sm->Wl[buf][n][t4 * 4]);
        }
#pragma unroll
        for (int kk = 0; kk < 2; kk++) {
            uint32_t ah[4], al[4];
            if (kk == 0) {
                ah[0] = fHh0.x; ah[1] = fHh1.x; ah[2] = fHh0.y; ah[3] = fHh1.y;
                al[0] = fHl0.x; al[1] = fHl1.x; al[2] = fHl0.y; al[3] = fHl1.y;
            } else {
                ah[0] = fHh0.z; ah[1] = fHh1.z; ah[2] = fHh0.w; ah[3] = fHh1.w;
                al[0] = fHl0.z; al[1] = fHl1.z; al[2] = fHl0.w; al[3] = fHl1.w;
            }
#pragma unroll
            for (int gg = 0; gg < 4; gg++) {
                uint32_t bh0 = kk ? fBh[gg].z : fBh[gg].x;
                uint32_t bh1 = kk ? fBh[gg].w : fBh[gg].y;
                uint32_t bl0 = kk ? fBl[gg].z : fBl[gg].x;
                uint32_t bl1 = kk ? fBl[gg].w : fBl[gg].y;
                mma8(acc[gg], ah, bh0, bh1);
                mma8(acc[gg], ah, bl0, bl1);
                mma8(acc[gg], al, bh0, bh1);
            }
        }
        __syncthreads();
        if (c + 2 < NCH) { issue(c + 2, buf); CP_COMMIT; }
    }

    const int idx = wj * 8 + t4 * 2;                    // even
    const int pj = j0 + (((idx & 3) << 2) | (idx >> 2));  // store col (perm), pj+4 = next
    const int jb = j0 + idx;                            // logical col (gpre/bias/c)
#pragma unroll
    for (int rr = 0; rr < 2; rr++) {
        const int m = m0 + wm * 16 + g8 + rr * 8;
        bool act = true;
        if (qlen) act = t < qlen[m / cfg::NC];
        const float* gp = L2K ? gpre_or_bias
                              : (gpre_or_bias + ((size_t)m * Tsteps + t) * 2048);
        float2 bi = *(const float2*)(gp + jb);
        float2 bf = *(const float2*)(gp + 512 + jb);
        float2 bg = *(const float2*)(gp + 1024 + jb);
        float2 bo = *(const float2*)(gp + 1536 + jb);
        const size_t offc = (size_t)m * 512 + jb;
        const size_t off0 = (size_t)m * 512 + pj;
        const size_t off1 = off0 + 4;
        float2 co = *(const float2*)(cp + offc);
        float gi0 = acc[0][rr * 2 + 0] + bi.x, gi1 = acc[0][rr * 2 + 1] + bi.y;
        float gf0 = acc[1][rr * 2 + 0] + bf.x, gf1 = acc[1][rr * 2 + 1] + bf.y;
        float gg0 = acc[2][rr * 2 + 0] + bg.x, gg1 = acc[2][rr * 2 + 1] + bg.y;
        float go0 = acc[3][rr * 2 + 0] + bo.x, go1 = acc[3][rr * 2 + 1] + bo.y;
        float cn0 = sigm(gf0) * co.x + sigm(gi0) * tanhf(gg0);
        float cn1 = sigm(gf1) * co.y + sigm(gi1) * tanhf(gg1);
        float hn0 = sigm(go0) * tanhf(cn0);
        float hn1 = sigm(go1) * tanhf(cn1);
        float h0h, h0l, h1h_, h1l_;
        fsplit(hn0, h0h, h0l); fsplit(hn1, h1h_, h1l_);
        if (!L2K) {
            hr_h[off0] = h0h; hr_l[off0] = h0l;
            hr_h[off1] = h1h_; hr_l[off1] = h1l_;
        }
        if (!act) {
            hn0 = hp_h[off0] + hp_l[off0];
            hn1 = hp_h[off1] + hp_l[off1];
            fsplit(hn0, h0h, h0l); fsplit(hn1, h1h_, h1l_);
            cn0 = co.x; cn1 = co.y;
        }
        hn_h[off0] = h0h; hn_l[off0] = h0l;
        hn_h[off1] = h1h_; hn_l[off1] = h1l_;
        *(float2*)(cn + offc) = make_float2(cn0, cn1);
    }
}

__global__ void __launch_bounds__(128, 3) recurrence_k(
    float* __restrict__ S, const float* __restrict__ b_v2,
    const float* __restrict__ b_t2, const int* __restrict__ qlen)
{
    using namespace cfg;
    __shared__ StepSmem sm;
    const int blk = blockIdx.x;
    const int gtid = blk * 128 + threadIdx.x;
    int bar = 0;

    const float* GV = S + OFF_GV;
    const float* GT = S + OFF_GT;
    const float* Wv1h = S + OFF_W512 + 0 * SZW;  const float* Wv1l = S + OFF_W512 + 1 * SZW;
    const float* Wi2h = S + OFF_W512 + 2 * SZW;  const float* Wi2l = S + OFF_W512 + 3 * SZW;
    const float* Wv2h = S + OFF_W512 + 4 * SZW;  const float* Wv2l = S + OFF_W512 + 5 * SZW;
    const float* Wt1h = S + OFF_W512 + 6 * SZW;  const float* Wt1l = S + OFF_W512 + 7 * SZW;
    const float* Wti2h = S + OFF_W512 + 8 * SZW; const float* Wti2l = S + OFF_W512 + 9 * SZW;
    const float* Wt2h = S + OFF_W512 + 10 * SZW; const float* Wt2l = S + OFF_W512 + 11 * SZW;
    float* VSA = S + OFF_VSA;  float* VSB = S + OFF_VSB;
    float* VRh = S + OFF_VRH;  float* VRl = S + OFF_VRL;
    float* TSA = S + OFF_TSA;  float* TSB = S + OFF_TSB;
    float* TRh = S + OFF_TRH;  float* TRl = S + OFF_TRL;

    for (int i = gtid; i < 6 * BH; i += NBLK * 128) VSA[i] = 0.f;
    gridbar(bar++);

    const int vm0 = (blk & 1) * 32;
    const int vj0 = (blk >> 1) * 16;
    for (int t = 0; t < F; t++) {
        float* cur = (t & 1) ? VSB : VSA;
        float* nxt = (t & 1) ? VSA : VSB;
        if (blk < 64)
            step_tile<false>(cur, cur + BH, Wv1h, Wv1l,
                             nullptr, nullptr, nullptr, nullptr,
                             GV, t, F,
                             cur, cur + BH, cur + 2 * BH,
                             nxt, nxt + BH, nxt + 2 * BH,
                             VRh, VRl, nullptr, vm0, vj0, &sm);
        gridbar(bar++);
        if (blk < 64)
            step_tile<true>(VRh, VRl, Wi2h, Wi2l,
                            cur + 3 * BH, cur + 4 * BH, Wv2h, Wv2l,
                            b_v2, t, F,
                            cur + 3 * BH, cur + 4 * BH, cur + 5 * BH,
                            nxt + 3 * BH, nxt + 4 * BH, nxt + 5 * BH,
                            nullptr, nullptr, nullptr, vm0, vj0, &sm);
        gridbar(bar++);
    }

    // broadcast video finals (VSA after 20 steps) to text states, plane-wise
    for (int i = gtid; i < 6 * MH; i += NBLK * 128) {
        int a = i / MH;
        int r = i - a * MH;
        int m = r >> 9, jj = r & 511;
        TSA[i] = __ldcg(VSA + (size_t)a * BH + (size_t)(m / NC) * H + jj);
    }
    gridbar(bar++);

    const int tm0 = (blk % 10) * 32;
    const int tj0 = (blk / 10) * 16;
    for (int t = 0; t < L; t++) {
        float* cur = (t & 1) ? TSB : TSA;
        float* nxt = (t & 1) ? TSA : TSB;
        step_tile<false>(cur, cur + MH, Wt1h, Wt1l,
                         nullptr, nullptr, nullptr, nullptr,
                         GT, t, L,
                         cur, cur + MH, cur + 2 * MH,
                         nxt, nxt + MH, nxt + 2 * MH,
                         TRh, TRl, qlen, tm0, tj0, &sm);
        gridbar(bar++);
        step_tile<true>(TRh, TRl, Wti2h, Wti2l,
                        cur + 3 * MH, cur + 4 * MH, Wt2h, Wt2l,
                        b_t2, t, L,
                        cur + 3 * MH, cur + 4 * MH, cur + 5 * MH,
                        nxt + 3 * MH, nxt + 4 * MH, nxt + 5 * MH,
                        nullptr, nullptr, qlen, tm0, tj0, &sm);
        gridbar(bar++);
    }
}

// ---------------------------------------------------------------------------
// Staging + small kernels
// ---------------------------------------------------------------------------
__global__ void zero_bars_k() { if (threadIdx.x < 128) g_bars[threadIdx.x] = 0u; }

__global__ void split_perm_k(const float* __restrict__ src, float* __restrict__ dh,
                             float* __restrict__ dl, int total, int K) {
    int i = blockIdx.x * 256 + threadIdx.x;
    if (i >= total) return;
    int n = i / K, p = i - n * K;
    float x = src[(size_t)n * K + perm16(p)];
    float h, l; fsplit(x, h, l);
    dh[i] = h; dl[i] = l;
}

__global__ void pad_split_perm_k(const float* __restrict__ src, float* __restrict__ dh,
                                 float* __restrict__ dl, int total, int K, int Ksrc) {
    int i = blockIdx.x * 256 + threadIdx.x;
    if (i >= total) return;
    int n = i / K, p = i - n * K;
    int k = perm16(p);
    float x = (k < Ksrc) ? src[(size_t)n * Ksrc + k] : 0.f;
    float h, l; fsplit(x, h, l);
    dh[i] = h; dl[i] = l;
}

__global__ void embed_split_k(const int* __restrict__ q, const float* __restrict__ emb,
                              float* __restrict__ dh, float* __restrict__ dl) {
    int i = blockIdx.x * 256 + threadIdx.x;
    if (i >= cfg::MT * cfg::L * cfg::EP) return;
    int r = i / cfg::EP, p = i - r * cfg::EP;
    int k = perm16(p);
    float x = (k < cfg::E) ? emb[(size_t)q[r] * cfg::E + k] : 0.f;
    float h, l; fsplit(x, h, l);
    dh[i] = h; dl[i] = l;
}

__global__ void reduce4_k(const float* __restrict__ P, const float* __restrict__ bias,
                          float* __restrict__ out) {
    int i = blockIdx.x * 256 + threadIdx.x;
    const int total = 1280 * 2048;
    if (i >= total) return;
    float v = (P[i] + P[i + (size_t)total]) + (P[i + 2ull * total] + P[i + 3ull * total]);
    out[i] = v + bias[i & 2047];
}

__global__ void concat_split_k(const float* __restrict__ TS, float* __restrict__ STh,
                               float* __restrict__ STl) {
    int i = blockIdx.x * 256 + threadIdx.x;
    if (i >= cfg::MT * 1024) return;
    int m = i >> 10, k = i & 1023;
    const float* h1h = TS;                 const float* h1l = TS + cfg::MH;
    const float* h2h = TS + 3ull * cfg::MH; const float* h2l = TS + 4ull * cfg::MH;
    float h, l;
    if (k < 512) { h = h1h[(size_t)m * 512 + k]; l = h1l[(size_t)m * 512 + k]; }
    else         { h = h2h[(size_t)m * 512 + k - 512]; l = h2l[(size_t)m * 512 + k - 512]; }
    STh[i] = h; STl[i] = l;
}

__global__ void rowdot_k(const float* __restrict__ fe, const float* __restrict__ w,
                         const float* __restrict__ b, float* __restrict__ out) {
    int warp = (blockIdx.x * blockDim.x + threadIdx.x) >> 5;
    int lane = threadIdx.x & 31;
    if (warp >= cfg::MT) return;
    const float* row = fe + (size_t)warp * 1024;
    float s = 0.f;
    for (int k = lane; k < 1024; k += 32) s += row[k] * w[k];
#pragma unroll
    for (int o = 16; o; o >>= 1) s += __shfl_xor_sync(0xffffffffu, s, o);
    if (lane == 0) out[warp] = s + b[0];
}

__global__ void finalize_k(const float* __restrict__ outv, float* __restrict__ dout,
                           int out_size) {
    int i = blockIdx.x * 256 + threadIdx.x;
    if (i >= out_size) return;
    if (i < cfg::MT) {
        dout[i] = outv[i];
    } else if (i < cfg::MT + cfg::B) {
        int b = i - cfg::MT;
        float best = outv[b * cfg::NC]; int bi = 0;
#pragma unroll
        for (int nc = 1; nc < cfg::NC; nc++) {
            float v = outv[b * cfg::NC + nc];
            if (v > best) { best = v; bi = nc; }
        }
        dout[i] = (float)bi;
    } else {
        dout[i] = 0.f;
    }
}

// ---------------------------------------------------------------------------
// Host launcher
// ---------------------------------------------------------------------------
extern "C" void kernel_launch(void* const* d_in, const int* in_sizes, int n_in,
                              void* d_out, int out_size) {
    using namespace cfg;
    const float* vf       = (const float*)d_in[0];
    const int*   questions= (const int*)  d_in[1];
    const int*   qlen     = (const int*)  d_in[2];
    const float* embw     = (const float*)d_in[3];
    const float* Wih_t1   = (const float*)d_in[4];
    const float* Whh_t1   = (const float*)d_in[5];
    const float* b_t1     = (const float*)d_in[6];
    const float* Wih_t2   = (const float*)d_in[7];
    const float* Whh_t2   = (const float*)d_in[8];
    const float* b_t2     = (const float*)d_in[9];
    const float* Wih_v1   = (const float*)d_in[10];
    const float* Whh_v1   = (const float*)d_in[11];
    const float* b_v1     = (const float*)d_in[12];
    const float* Wih_v2   = (const float*)d_in[13];
    const float* Whh_v2   = (const float*)d_in[14];
    const float* b_v2     = (const float*)d_in[15];
    const float* dec1_w   = (const float*)d_in[16];
    const float* dec1_b   = (const float*)d_in[17];
    const float* dec2_w   = (const float*)d_in[18];
    const float* dec2_b   = (const float*)d_in[19];
    (void)in_sizes; (void)n_in;

    float* S = nullptr;
    cudaGetSymbolAddress((void**)&S, g_scratch);

    auto SP = [&](const float* src, size_t oh, size_t ol, int N_, int K_) {
        int tot = N_ * K_;
        split_perm_k<<<(tot + 255) / 256, 256>>>(src, S + oh, S + ol, tot, K_);
    };

    zero_bars_k<<<1, 128>>>();

    // Stage pre-split / permuted operand planes
    SP(vf,     OFF_VFH,  OFF_VFL,  1280, C);
    SP(Wih_v1, OFF_WV1H, OFF_WV1L, G4, C);
    SP(Whh_v1, OFF_W512 + 0 * SZW, OFF_W512 + 1 * SZW, G4, 512);
    SP(Wih_v2, OFF_W512 + 2 * SZW, OFF_W512 + 3 * SZW, G4, 512);
    SP(Whh_v2, OFF_W512 + 4 * SZW, OFF_W512 + 5 * SZW, G4, 512);
    SP(Whh_t1, OFF_W512 + 6 * SZW, OFF_W512 + 7 * SZW, G4, 512);
    SP(Wih_t2, OFF_W512 + 8 * SZW, OFF_W512 + 9 * SZW, G4, 512);
    SP(Whh_t2, OFF_W512 + 10 * SZW, OFF_W512 + 11 * SZW, G4, 512);
    SP(dec1_w, OFF_D1H, OFF_D1L, 1024, 1024);
    pad_split_perm_k<<<(G4 * EP + 255) / 256, 256>>>(Wih_t1, S + OFF_WT1H, S + OFF_WT1L,
                                                     G4 * EP, EP, E);
    embed_split_k<<<(MT * L * EP + 255) / 256, 256>>>(questions, embw,
                                                      S + OFF_XTH, S + OFF_XTL);

    // GV: split-K=4 -> partials -> reduce(+bias)
    gemm3_tc<<<dim3(G4 / 128, 1280 / 64, 4), 256>>>(
        S + OFF_VFH, S + OFF_VFL, S + OFF_WV1H, S + OFF_WV1L,
        nullptr, S + OFF_GVP, 1280, G4, C, C / 4);
    reduce4_k<<<(1280 * 2048 + 255) / 256, 256>>>(S + OFF_GVP, b_v1, S + OFF_GV);

    // GT (no split-K)
    gemm3_tc<<<dim3(G4 / 128, 6400 / 64, 1), 256>>>(
        S + OFF_XTH, S + OFF_XTL, S + OFF_WT1H, S + OFF_WT1L,
        b_t1, S + OFF_GT, 6400, G4, EP, EP);

    // Persistent recurrence
    recurrence_k<<<NBLK, 128>>>(S, b_v2, b_t2, qlen);

    // Decoder
    concat_split_k<<<(MT * 1024 + 255) / 256, 256>>>(S + OFF_TSA, S + OFF_STH, S + OFF_STL);
    gemm3_tc<<<dim3(1024 / 128, MT / 64, 1), 256>>>(
        S + OFF_STH, S + OFF_STL, S + OFF_D1H, S + OFF_D1L,
        dec1_b, S + OFF_FE, MT, 1024, 1024, 1024);
    rowdot_k<<<40, 256>>>(S + OFF_FE, dec2_w, dec2_b, S + OFF_OUT);
    finalize_k<<<(out_size + 255) / 256, 256>>>(S + OFF_OUT, (float*)d_out, out_size);
}